// round 14
// baseline (speedup 1.0000x reference)
#include <cuda_runtime.h>
#include <cuda_fp16.h>
#include <stdint.h>
#include <math.h>

#define HEADS 16
#define DH    64
#define BATCH 8
#define SEQ   512
#define DMODEL 1024
#define INNER 1024            // HEADS*DH
#define QKV_N 3072            // 3*INNER
#define NTOK  4096            // BATCH*SEQ

// Scratch (device globals: allocation-free, graph-capture safe)
__device__ __half g_xh[(size_t)NTOK * DMODEL];               // 8 MB
__device__ __half g_qkvh[(size_t)NTOK * QKV_N];              // 24 MB
__device__ __half g_dotsh[(size_t)BATCH * HEADS * SEQ * SEQ];// 64 MB fp16 logits
__device__ __half g_attnh[(size_t)BATCH * HEADS * SEQ * SEQ];// 64 MB
__device__ __half g_avh[(size_t)NTOK * INNER];               // 8 MB
__device__ __half g_wqkvT[(size_t)QKV_N * DMODEL];           // 6 MB [n][k]
__device__ __half g_woutT[(size_t)DMODEL * INNER];           // 2 MB [n][k]
__device__ __half g_vT[(size_t)BATCH * HEADS * DH * SEQ];    // 8 MB [b][h][d][j]

// ---------------------------------------------------------------------------
__device__ __forceinline__ void mma16(float* c, const uint32_t* a, const uint32_t* b) {
    asm volatile(
        "mma.sync.aligned.m16n8k16.row.col.f32.f16.f16.f32 "
        "{%0,%1,%2,%3}, {%4,%5,%6,%7}, {%8,%9}, {%0,%1,%2,%3};"
        : "+f"(c[0]), "+f"(c[1]), "+f"(c[2]), "+f"(c[3])
        : "r"(a[0]), "r"(a[1]), "r"(a[2]), "r"(a[3]),
          "r"(b[0]), "r"(b[1]));
}

__device__ __forceinline__ void ldsm_x4(uint32_t* r, const __half* p) {
    uint32_t addr = (uint32_t)__cvta_generic_to_shared(p);
    asm volatile(
        "ldmatrix.sync.aligned.m8n8.x4.shared.b16 {%0,%1,%2,%3}, [%4];"
        : "=r"(r[0]), "=r"(r[1]), "=r"(r[2]), "=r"(r[3]) : "r"(addr));
}

__device__ __forceinline__ void cp16(uint32_t smem_dst, const void* gsrc) {
    asm volatile("cp.async.cg.shared.global [%0], [%1], 16;"
                 :: "r"(smem_dst), "l"(gsrc));
}

// ---------------------------------------------------------------------------
// Prep kernels
// ---------------------------------------------------------------------------
__global__ void __launch_bounds__(256) x_cvt(
    const float* __restrict__ in, __half* __restrict__ out)
{
    size_t i = ((size_t)blockIdx.x * 256 + threadIdx.x) * 8;
    float4 a = *reinterpret_cast<const float4*>(in + i);
    float4 b = *reinterpret_cast<const float4*>(in + i + 4);
    __half2 h0 = __floats2half2_rn(a.x, a.y);
    __half2 h1 = __floats2half2_rn(a.z, a.w);
    __half2 h2 = __floats2half2_rn(b.x, b.y);
    __half2 h3 = __floats2half2_rn(b.z, b.w);
    uint4 u;
    u.x = *reinterpret_cast<uint32_t*>(&h0);
    u.y = *reinterpret_cast<uint32_t*>(&h1);
    u.z = *reinterpret_cast<uint32_t*>(&h2);
    u.w = *reinterpret_cast<uint32_t*>(&h3);
    *reinterpret_cast<uint4*>(out + i) = u;
}

__global__ void __launch_bounds__(256) transpose_cvt(
    const float* __restrict__ in, __half* __restrict__ out, int K, int N)
{
    __shared__ float tile[32][33];
    const int k0 = blockIdx.y * 32, n0 = blockIdx.x * 32;
    const int tx = threadIdx.x & 31, ty = threadIdx.x >> 5;
    #pragma unroll
    for (int t = 0; t < 4; t++)
        tile[ty + t * 8][tx] = in[(size_t)(k0 + ty + t * 8) * N + n0 + tx];
    __syncthreads();
    #pragma unroll
    for (int t = 0; t < 4; t++)
        out[(size_t)(n0 + ty + t * 8) * K + k0 + tx] =
            __float2half_rn(tile[tx][ty + t * 8]);
}

__global__ void __launch_bounds__(256) v_transpose(
    const __half* __restrict__ qkvh, __half* __restrict__ vT)
{
    __shared__ __half tile[32][34];
    const int bh = blockIdx.z, b = bh >> 4, h = bh & 15;
    const int j0 = blockIdx.x * 32, d0 = blockIdx.y * 32;
    const int tx = threadIdx.x & 31, ty = threadIdx.x >> 5;
    const __half* src = qkvh + (size_t)b * SEQ * QKV_N + 2 * INNER + h * DH;
    #pragma unroll
    for (int t = 0; t < 4; t++)
        tile[ty + t * 8][tx] = src[(size_t)(j0 + ty + t * 8) * QKV_N + d0 + tx];
    __syncthreads();
    __half* dst = vT + (size_t)bh * DH * SEQ;
    #pragma unroll
    for (int t = 0; t < 4; t++)
        dst[(size_t)(d0 + ty + t * 8) * SEQ + j0 + tx] = tile[tx][ty + t * 8];
}

// ---------------------------------------------------------------------------
// fp16 tensor-core GEMM: cp.async 2-stage pipeline, BK=64 per stage,
// ldmatrix fragments, LK=72. BN=64 warp tile -> 3 CTAs/SM without spill.
// MODE 0: QKV (C fp16)   MODE 1: OUT (+bias, C fp32)
// MODE 2: AV (per bh, C fp16)   MODE 3: DOTS (per bh, C fp16, alpha=0.125)
// ---------------------------------------------------------------------------
template<int MODE, int BM, int BN, int KTOT>
__global__ void __launch_bounds__(256, 3) hgemm(
    const __half* __restrict__ gA, const __half* __restrict__ gB,
    const float* __restrict__ bias, void* __restrict__ gC)
{
    constexpr bool CHALF = (MODE != 1);
    constexpr float ALPHA = (MODE == 3) ? 0.125f : 1.0f;
    constexpr int MI = BM / 64;
    constexpr int NP = BN / 32;
    constexpr int LK = 72;
    constexpr int S  = 2;
    constexpr int BK = 64;
    constexpr int T  = KTOT / BK;
    constexpr int NLDA = BM / 32;
    constexpr int NLDB = BN / 32;

    __shared__ __align__(16) __half sA[S][BM * LK];
    __shared__ __align__(16) __half sB[S][BN * LK];

    const int tid  = threadIdx.x;
    const int row0 = blockIdx.y * BM;
    const int col0 = blockIdx.x * BN;

    const __half* A;
    const __half* B;
    float*  Cf = nullptr;
    __half* Ch = nullptr;
    int lda, ldb, ldc;

    if (MODE == 0) {
        A = gA; lda = DMODEL; B = gB; ldb = DMODEL;
        Ch = (__half*)gC; ldc = QKV_N;
    } else if (MODE == 1) {
        A = gA; lda = DMODEL; B = gB; ldb = DMODEL;
        Cf = (float*)gC; ldc = DMODEL;
    } else if (MODE == 2) {
        const int bh = blockIdx.z, b = bh >> 4, h = bh & 15;
        A = gA + (size_t)bh * SEQ * SEQ;            lda = SEQ;
        B = gB + (size_t)bh * DH * SEQ;             ldb = SEQ;
        Ch = (__half*)gC + (size_t)b * SEQ * INNER + (size_t)h * DH; ldc = INNER;
    } else {
        const int bh = blockIdx.z, b = bh >> 4, h = bh & 15;
        A = gA + (size_t)b * SEQ * QKV_N + (size_t)h * DH;          lda = QKV_N;
        B = gB + (size_t)b * SEQ * QKV_N + INNER + (size_t)h * DH;  ldb = QKV_N;
        Ch = (__half*)gC + (size_t)bh * SEQ * SEQ;                  ldc = SEQ;
    }

    const int warp = tid >> 5, lane = tid & 31;
    const int wm = warp >> 1, wn = warp & 1;
    const int g = lane >> 2, t4 = lane & 3;
    const int lmRow = lane & 15;
    const int lmK8  = (lane >> 4) * 8;

    const int cR = tid >> 3;
    const int cC = tid & 7;

    const uint32_t sA0 = (uint32_t)__cvta_generic_to_shared(&sA[0][0]);
    const uint32_t sB0 = (uint32_t)__cvta_generic_to_shared(&sB[0][0]);

    auto cpStage = [&](int kt, int st) {
        const int k0 = kt * BK;
        #pragma unroll
        for (int p = 0; p < NLDA; p++) {
            int r = cR + p * 32;
            cp16(sA0 + (uint32_t)((st * BM + r) * LK + cC * 8) * 2,
                 &A[(size_t)(row0 + r) * lda + k0 + cC * 8]);
        }
        #pragma unroll
        for (int p = 0; p < NLDB; p++) {
            int r = cR + p * 32;
            cp16(sB0 + (uint32_t)((st * BN + r) * LK + cC * 8) * 2,
                 &B[(size_t)(col0 + r) * ldb + k0 + cC * 8]);
        }
    };

    float acc[MI][NP * 2][4] = {};

    cpStage(0, 0);
    asm volatile("cp.async.commit_group;");

    for (int t = 0; t < T; t++) {
        asm volatile("cp.async.wait_group 0;");
        __syncthreads();

        if (t + 1 < T) cpStage(t + 1, (t + 1) & 1);
        asm volatile("cp.async.commit_group;");

        const __half* cA = sA[t & 1];
        const __half* cB = sB[t & 1];

        #pragma unroll
        for (int kk = 0; kk < 4; kk++) {
            const int kc = kk * 16 + lmK8;
            uint32_t af[MI][4];
            #pragma unroll
            for (int mi = 0; mi < MI; mi++) {
                int r = wm * (BM / 4) + mi * 16 + lmRow;
                ldsm_x4(af[mi], &cA[r * LK + kc]);
            }
            uint32_t bfp[NP][4];
            #pragma unroll
            for (int p = 0; p < NP; p++) {
                int c = wn * (BN / 2) + p * 16 + lmRow;
                ldsm_x4(bfp[p], &cB[c * LK + kc]);
            }
            #pragma unroll
            for (int mi = 0; mi < MI; mi++)
                #pragma unroll
                for (int p = 0; p < NP; p++) {
                    uint32_t b0[2] = { bfp[p][0], bfp[p][2] };
                    uint32_t b1[2] = { bfp[p][1], bfp[p][3] };
                    mma16(acc[mi][2 * p],     af[mi], b0);
                    mma16(acc[mi][2 * p + 1], af[mi], b1);
                }
        }
    }

    #pragma unroll
    for (int mi = 0; mi < MI; mi++) {
        int r = row0 + wm * (BM / 4) + mi * 16 + g;
        #pragma unroll
        for (int ni = 0; ni < NP * 2; ni++) {
            int c = col0 + wn * (BN / 2) + (ni >> 1) * 16 + (ni & 1) * 8 + 2 * t4;
            float* a = acc[mi][ni];
            if (CHALF) {
                __half2 hv0 = __floats2half2_rn(a[0] * ALPHA, a[1] * ALPHA);
                __half2 hv1 = __floats2half2_rn(a[2] * ALPHA, a[3] * ALPHA);
                *reinterpret_cast<__half2*>(&Ch[(size_t)r * ldc + c]) = hv0;
                *reinterpret_cast<__half2*>(&Ch[(size_t)(r + 8) * ldc + c]) = hv1;
            } else {
                float b0 = bias[c], b1 = bias[c + 1];
                float2 v0, v1;
                v0.x = a[0] + b0; v0.y = a[1] + b1;
                v1.x = a[2] + b0; v1.y = a[3] + b1;
                *reinterpret_cast<float2*>(&Cf[(size_t)r * ldc + c]) = v0;
                *reinterpret_cast<float2*>(&Cf[(size_t)(r + 8) * ldc + c]) = v1;
            }
        }
    }
}

// ---------------------------------------------------------------------------
// Fused softmax + head-mix + LayerNorm: reads fp16 logits, writes fp16 attn.
// ---------------------------------------------------------------------------
__global__ void __launch_bounds__(512) softmax_mix_ln_kernel(
    const __half* __restrict__ dotsh, __half* __restrict__ attnh,
    const float* __restrict__ W,
    const float* __restrict__ gamma, const float* __restrict__ beta)
{
    const int bi = blockIdx.x;
    const int b  = bi >> 9;
    const int i  = bi & 511;

    __shared__ float sc[HEADS][SEQ];
    __shared__ float wmat[HEADS][HEADS];
    __shared__ float sg[HEADS], sb[HEADS];

    const int tid = threadIdx.x;
    if (tid < 256) wmat[tid >> 4][tid & 15] = W[tid];
    if (tid < HEADS) { sg[tid] = gamma[tid]; sb[tid] = beta[tid]; }

    // Load 16 heads x 512 fp16 logits (8192 halves = 1024 x 16B chunks)
    #pragma unroll
    for (int t = 0; t < 2; t++) {
        int idx = tid + t * 512;         // 0..1023
        int h   = idx >> 6;              // 64 chunks per head row
        int c8  = idx & 63;
        uint4 u = *reinterpret_cast<const uint4*>(
            &dotsh[((size_t)(b * HEADS + h) * SEQ + i) * SEQ + c8 * 8]);
        const __half2* hp = reinterpret_cast<const __half2*>(&u);
        #pragma unroll
        for (int k = 0; k < 4; k++) {
            float2 f = __half22float2(hp[k]);
            sc[h][c8 * 8 + 2 * k]     = f.x;
            sc[h][c8 * 8 + 2 * k + 1] = f.y;
        }
    }
    __syncthreads();

    const int h = tid >> 5, lane = tid & 31;
    {
        float mx = -1e30f;
        #pragma unroll
        for (int t = 0; t < 16; t++) mx = fmaxf(mx, sc[h][lane + t * 32]);
        #pragma unroll
        for (int o = 16; o > 0; o >>= 1)
            mx = fmaxf(mx, __shfl_xor_sync(0xffffffffu, mx, o));
        float s = 0.f;
        #pragma unroll
        for (int t = 0; t < 16; t++) {
            float e = __expf(sc[h][lane + t * 32] - mx);
            sc[h][lane + t * 32] = e;
            s += e;
        }
        #pragma unroll
        for (int o = 16; o > 0; o >>= 1)
            s += __shfl_xor_sync(0xffffffffu, s, o);
        float inv = 1.f / s;
        #pragma unroll
        for (int t = 0; t < 16; t++) sc[h][lane + t * 32] *= inv;
    }
    __syncthreads();

    {
        const int j = tid;
        float a[HEADS];
        #pragma unroll
        for (int hh = 0; hh < HEADS; hh++) a[hh] = sc[hh][j];
        float mixed[HEADS];
        #pragma unroll
        for (int gg = 0; gg < HEADS; gg++) {
            float s = 0.f;
            #pragma unroll
            for (int hh = 0; hh < HEADS; hh++) s = fmaf(a[hh], wmat[hh][gg], s);
            mixed[gg] = s;
        }
        float mean = 0.f;
        #pragma unroll
        for (int gg = 0; gg < HEADS; gg++) mean += mixed[gg];
        mean *= (1.f / HEADS);
        float var = 0.f;
        #pragma unroll
        for (int gg = 0; gg < HEADS; gg++) {
            float d = mixed[gg] - mean;
            var = fmaf(d, d, var);
        }
        var *= (1.f / HEADS);
        float inv = rsqrtf(var + 1e-3f);
        #pragma unroll
        for (int gg = 0; gg < HEADS; gg++) {
            float y = (mixed[gg] - mean) * inv * sg[gg] + sb[gg];
            attnh[((size_t)(b * HEADS + gg) * SEQ + i) * SEQ + j] =
                __float2half_rn(y);
        }
    }
}

// ---------------------------------------------------------------------------
extern "C" void kernel_launch(void* const* d_in, const int* in_sizes, int n_in,
                              void* d_out, int out_size)
{
    const float* x        = (const float*)d_in[0];
    const float* w_qkv    = (const float*)d_in[1];
    const float* reattn_w = (const float*)d_in[2];
    const float* ln_gamma = (const float*)d_in[3];
    const float* ln_beta  = (const float*)d_in[4];
    const float* w_out    = (const float*)d_in[5];
    const float* b_out    = (const float*)d_in[6];
    float* out = (float*)d_out;

    __half *xh = nullptr, *qkvh = nullptr, *attnh = nullptr, *avh = nullptr;
    __half *wqkvT = nullptr, *woutT = nullptr, *vT = nullptr, *dotsh = nullptr;
    cudaGetSymbolAddress((void**)&xh,    g_xh);
    cudaGetSymbolAddress((void**)&qkvh,  g_qkvh);
    cudaGetSymbolAddress((void**)&dotsh, g_dotsh);
    cudaGetSymbolAddress((void**)&attnh, g_attnh);
    cudaGetSymbolAddress((void**)&avh,   g_avh);
    cudaGetSymbolAddress((void**)&wqkvT, g_wqkvT);
    cudaGetSymbolAddress((void**)&woutT, g_woutT);
    cudaGetSymbolAddress((void**)&vT,    g_vT);

    dim3 blk(256);

    // 0) prep
    x_cvt<<<(NTOK * DMODEL) / (256 * 8), blk>>>(x, xh);
    transpose_cvt<<<dim3(QKV_N / 32, DMODEL / 32), blk>>>(w_qkv, wqkvT, DMODEL, QKV_N);
    transpose_cvt<<<dim3(DMODEL / 32, DMODEL / 32), blk>>>(w_out, woutT, DMODEL, DMODEL);

    // 1) QKV projection -> fp16
    hgemm<0, 128, 64, 1024><<<dim3(QKV_N / 64, NTOK / 128), blk>>>(
        xh, wqkvT, nullptr, qkvh);

    // 1b) V transpose
    v_transpose<<<dim3(SEQ / 32, DH / 32, BATCH * HEADS), blk>>>(qkvh, vT);

    // 2) dots -> fp16 (alpha=0.125 applied pre-store; logits ~N(0,1))
    hgemm<3, 128, 64, 64><<<dim3(SEQ / 64, SEQ / 128, BATCH * HEADS), blk>>>(
        qkvh, qkvh, nullptr, dotsh);

    // 3) fused softmax + head mix + LayerNorm -> fp16
    softmax_mix_ln_kernel<<<BATCH * SEQ, 512>>>(dotsh, attnh, reattn_w, ln_gamma, ln_beta);

    // 4) AV -> fp16
    hgemm<2, 128, 64, 512><<<dim3(1, SEQ / 128, BATCH * HEADS), blk>>>(
        attnh, vT, nullptr, avh);

    // 5) output projection + bias -> fp32
    hgemm<1, 128, 64, 1024><<<dim3(DMODEL / 64, NTOK / 128), blk>>>(
        avh, woutT, b_out, out);
}

// round 15
// speedup vs baseline: 1.0649x; 1.0649x over previous
#include <cuda_runtime.h>
#include <cuda_fp16.h>
#include <stdint.h>
#include <math.h>

#define HEADS 16
#define DH    64
#define BATCH 8
#define SEQ   512
#define DMODEL 1024
#define INNER 1024            // HEADS*DH
#define QKV_N 3072            // 3*INNER
#define NTOK  4096            // BATCH*SEQ

// Scratch (device globals: allocation-free, graph-capture safe)
__device__ __half g_xh[(size_t)NTOK * DMODEL];               // 8 MB
__device__ __half g_qkvh[(size_t)NTOK * QKV_N];              // 24 MB
__device__ float  g_dots[(size_t)BATCH * HEADS * SEQ * SEQ]; // 128 MB fp32 logits
__device__ __half g_attnh[(size_t)BATCH * HEADS * SEQ * SEQ];// 64 MB
__device__ __half g_avh[(size_t)NTOK * INNER];               // 8 MB
__device__ __half g_wqkvT[(size_t)QKV_N * DMODEL];           // 6 MB [n][k]
__device__ __half g_woutT[(size_t)DMODEL * INNER];           // 2 MB [n][k]
__device__ __half g_vT[(size_t)BATCH * HEADS * DH * SEQ];    // 8 MB [b][h][d][j]

// ---------------------------------------------------------------------------
__device__ __forceinline__ void mma16(float* c, const uint32_t* a, const uint32_t* b) {
    asm volatile(
        "mma.sync.aligned.m16n8k16.row.col.f32.f16.f16.f32 "
        "{%0,%1,%2,%3}, {%4,%5,%6,%7}, {%8,%9}, {%0,%1,%2,%3};"
        : "+f"(c[0]), "+f"(c[1]), "+f"(c[2]), "+f"(c[3])
        : "r"(a[0]), "r"(a[1]), "r"(a[2]), "r"(a[3]),
          "r"(b[0]), "r"(b[1]));
}

__device__ __forceinline__ void ldsm_x4(uint32_t* r, const __half* p) {
    uint32_t addr = (uint32_t)__cvta_generic_to_shared(p);
    asm volatile(
        "ldmatrix.sync.aligned.m8n8.x4.shared.b16 {%0,%1,%2,%3}, [%4];"
        : "=r"(r[0]), "=r"(r[1]), "=r"(r[2]), "=r"(r[3]) : "r"(addr));
}

__device__ __forceinline__ void ldsm_x4_trans(uint32_t* r, const __half* p) {
    uint32_t addr = (uint32_t)__cvta_generic_to_shared(p);
    asm volatile(
        "ldmatrix.sync.aligned.m8n8.x4.trans.shared.b16 {%0,%1,%2,%3}, [%4];"
        : "=r"(r[0]), "=r"(r[1]), "=r"(r[2]), "=r"(r[3]) : "r"(addr));
}

__device__ __forceinline__ void cp16(uint32_t smem_dst, const void* gsrc) {
    asm volatile("cp.async.cg.shared.global [%0], [%1], 16;"
                 :: "r"(smem_dst), "l"(gsrc));
}

// ---------------------------------------------------------------------------
// Prep kernels
// ---------------------------------------------------------------------------
__global__ void __launch_bounds__(256) x_cvt(
    const float* __restrict__ in, __half* __restrict__ out)
{
    size_t i = ((size_t)blockIdx.x * 256 + threadIdx.x) * 8;
    float4 a = *reinterpret_cast<const float4*>(in + i);
    float4 b = *reinterpret_cast<const float4*>(in + i + 4);
    __half2 h0 = __floats2half2_rn(a.x, a.y);
    __half2 h1 = __floats2half2_rn(a.z, a.w);
    __half2 h2 = __floats2half2_rn(b.x, b.y);
    __half2 h3 = __floats2half2_rn(b.z, b.w);
    uint4 u;
    u.x = *reinterpret_cast<uint32_t*>(&h0);
    u.y = *reinterpret_cast<uint32_t*>(&h1);
    u.z = *reinterpret_cast<uint32_t*>(&h2);
    u.w = *reinterpret_cast<uint32_t*>(&h3);
    *reinterpret_cast<uint4*>(out + i) = u;
}

__global__ void __launch_bounds__(256) transpose_cvt(
    const float* __restrict__ in, __half* __restrict__ out, int K, int N)
{
    __shared__ float tile[32][33];
    const int k0 = blockIdx.y * 32, n0 = blockIdx.x * 32;
    const int tx = threadIdx.x & 31, ty = threadIdx.x >> 5;
    #pragma unroll
    for (int t = 0; t < 4; t++)
        tile[ty + t * 8][tx] = in[(size_t)(k0 + ty + t * 8) * N + n0 + tx];
    __syncthreads();
    #pragma unroll
    for (int t = 0; t < 4; t++)
        out[(size_t)(n0 + ty + t * 8) * K + k0 + tx] =
            __float2half_rn(tile[tx][ty + t * 8]);
}

__global__ void __launch_bounds__(256) v_transpose(
    const __half* __restrict__ qkvh, __half* __restrict__ vT)
{
    __shared__ __half tile[32][34];
    const int bh = blockIdx.z, b = bh >> 4, h = bh & 15;
    const int j0 = blockIdx.x * 32, d0 = blockIdx.y * 32;
    const int tx = threadIdx.x & 31, ty = threadIdx.x >> 5;
    const __half* src = qkvh + (size_t)b * SEQ * QKV_N + 2 * INNER + h * DH;
    #pragma unroll
    for (int t = 0; t < 4; t++)
        tile[ty + t * 8][tx] = src[(size_t)(j0 + ty + t * 8) * QKV_N + d0 + tx];
    __syncthreads();
    __half* dst = vT + (size_t)bh * DH * SEQ;
    #pragma unroll
    for (int t = 0; t < 4; t++)
        dst[(size_t)(d0 + ty + t * 8) * SEQ + j0 + tx] = tile[tx][ty + t * 8];
}

// ---------------------------------------------------------------------------
// fp16 tensor-core GEMM (R12-proven): cp.async 2-stage, BK=64/stage, ldmatrix.
// MODE 0: QKV (C fp16)   MODE 1: OUT (+bias, C fp32)
// MODE 2: AV (per bh, C fp16)   MODE 3: DOTS (per bh, C fp32, *0.125)
// ---------------------------------------------------------------------------
template<int MODE, int BM, int BN, int KTOT>
__global__ void __launch_bounds__(256, 3) hgemm(
    const __half* __restrict__ gA, const __half* __restrict__ gB,
    const float* __restrict__ bias, void* __restrict__ gC)
{
    constexpr bool CHALF = (MODE == 0 || MODE == 2);
    constexpr int MI = BM / 64;
    constexpr int NP = BN / 32;
    constexpr int LK = 72;
    constexpr int S  = 2;
    constexpr int BK = 64;
    constexpr int T  = KTOT / BK;
    constexpr int NLDA = BM / 32;
    constexpr int NLDB = BN / 32;

    __shared__ __align__(16) __half sA[S][BM * LK];
    __shared__ __align__(16) __half sB[S][BN * LK];

    const int tid  = threadIdx.x;
    const int row0 = blockIdx.y * BM;
    const int col0 = blockIdx.x * BN;

    const __half* A;
    const __half* B;
    float*  Cf = nullptr;
    __half* Ch = nullptr;
    int lda, ldb, ldc;
    float alpha = 1.0f;

    if (MODE == 0) {
        A = gA; lda = DMODEL; B = gB; ldb = DMODEL;
        Ch = (__half*)gC; ldc = QKV_N;
    } else if (MODE == 1) {
        A = gA; lda = DMODEL; B = gB; ldb = DMODEL;
        Cf = (float*)gC; ldc = DMODEL;
    } else if (MODE == 2) {
        const int bh = blockIdx.z, b = bh >> 4, h = bh & 15;
        A = gA + (size_t)bh * SEQ * SEQ;            lda = SEQ;
        B = gB + (size_t)bh * DH * SEQ;             ldb = SEQ;
        Ch = (__half*)gC + (size_t)b * SEQ * INNER + (size_t)h * DH; ldc = INNER;
    } else {
        const int bh = blockIdx.z, b = bh >> 4, h = bh & 15;
        A = gA + (size_t)b * SEQ * QKV_N + (size_t)h * DH;          lda = QKV_N;
        B = gB + (size_t)b * SEQ * QKV_N + INNER + (size_t)h * DH;  ldb = QKV_N;
        Cf = (float*)gC + (size_t)bh * SEQ * SEQ;                   ldc = SEQ;
        alpha = 0.125f;
    }

    const int warp = tid >> 5, lane = tid & 31;
    const int wm = warp >> 1, wn = warp & 1;
    const int g = lane >> 2, t4 = lane & 3;
    const int lmRow = lane & 15;
    const int lmK8  = (lane >> 4) * 8;

    const int cR = tid >> 3;
    const int cC = tid & 7;

    const uint32_t sA0 = (uint32_t)__cvta_generic_to_shared(&sA[0][0]);
    const uint32_t sB0 = (uint32_t)__cvta_generic_to_shared(&sB[0][0]);

    auto cpStage = [&](int kt, int st) {
        const int k0 = kt * BK;
        #pragma unroll
        for (int p = 0; p < NLDA; p++) {
            int r = cR + p * 32;
            cp16(sA0 + (uint32_t)((st * BM + r) * LK + cC * 8) * 2,
                 &A[(size_t)(row0 + r) * lda + k0 + cC * 8]);
        }
        #pragma unroll
        for (int p = 0; p < NLDB; p++) {
            int r = cR + p * 32;
            cp16(sB0 + (uint32_t)((st * BN + r) * LK + cC * 8) * 2,
                 &B[(size_t)(col0 + r) * ldb + k0 + cC * 8]);
        }
    };

    float acc[MI][NP * 2][4] = {};

    cpStage(0, 0);
    asm volatile("cp.async.commit_group;");

    for (int t = 0; t < T; t++) {
        asm volatile("cp.async.wait_group 0;");
        __syncthreads();

        if (t + 1 < T) cpStage(t + 1, (t + 1) & 1);
        asm volatile("cp.async.commit_group;");

        const __half* cA = sA[t & 1];
        const __half* cB = sB[t & 1];

        #pragma unroll
        for (int kk = 0; kk < 4; kk++) {
            const int kc = kk * 16 + lmK8;
            uint32_t af[MI][4];
            #pragma unroll
            for (int mi = 0; mi < MI; mi++) {
                int r = wm * (BM / 4) + mi * 16 + lmRow;
                ldsm_x4(af[mi], &cA[r * LK + kc]);
            }
            uint32_t bfp[NP][4];
            #pragma unroll
            for (int p = 0; p < NP; p++) {
                int c = wn * (BN / 2) + p * 16 + lmRow;
                ldsm_x4(bfp[p], &cB[c * LK + kc]);
            }
            #pragma unroll
            for (int mi = 0; mi < MI; mi++)
                #pragma unroll
                for (int p = 0; p < NP; p++) {
                    uint32_t b0[2] = { bfp[p][0], bfp[p][2] };
                    uint32_t b1[2] = { bfp[p][1], bfp[p][3] };
                    mma16(acc[mi][2 * p],     af[mi], b0);
                    mma16(acc[mi][2 * p + 1], af[mi], b1);
                }
        }
    }

    #pragma unroll
    for (int mi = 0; mi < MI; mi++) {
        int r = row0 + wm * (BM / 4) + mi * 16 + g;
        #pragma unroll
        for (int ni = 0; ni < NP * 2; ni++) {
            int c = col0 + wn * (BN / 2) + (ni >> 1) * 16 + (ni & 1) * 8 + 2 * t4;
            float* a = acc[mi][ni];
            if (CHALF) {
                __half2 hv0 = __floats2half2_rn(a[0], a[1]);
                __half2 hv1 = __floats2half2_rn(a[2], a[3]);
                *reinterpret_cast<__half2*>(&Ch[(size_t)r * ldc + c]) = hv0;
                *reinterpret_cast<__half2*>(&Ch[(size_t)(r + 8) * ldc + c]) = hv1;
            } else {
                float b0 = 0.f, b1 = 0.f;
                if (MODE == 1) { b0 = bias[c]; b1 = bias[c + 1]; }
                float2 v0, v1;
                v0.x = a[0] * alpha + b0; v0.y = a[1] * alpha + b1;
                v1.x = a[2] * alpha + b0; v1.y = a[3] * alpha + b1;
                *reinterpret_cast<float2*>(&Cf[(size_t)r * ldc + c]) = v0;
                *reinterpret_cast<float2*>(&Cf[(size_t)(r + 8) * ldc + c]) = v1;
            }
        }
    }
}

// ---------------------------------------------------------------------------
// Fused softmax + TENSOR-CORE head-mix + LayerNorm.
// 512 threads. Softmax per head entirely in registers (warp w = head w).
// Normalized attn -> fp16 smem; mix = W^T[16x16] @ attn[16x512] via mma;
// mixed -> fp32 smem; LN per thread j.
// ---------------------------------------------------------------------------
__global__ void __launch_bounds__(512) softmax_mix_ln_kernel(
    const float* __restrict__ dots, __half* __restrict__ attnh,
    const float* __restrict__ W,
    const float* __restrict__ gamma, const float* __restrict__ beta)
{
    __shared__ __align__(16) __half sch[HEADS][520];   // fp16 attn (ldsm pad)
    __shared__ float smix[HEADS][516];                 // fp32 mixed (STS pad)
    __shared__ __align__(16) __half wh[16][24];        // W^T [g][h] (ldsm pad)
    __shared__ float sg[16], sb[16];

    const int bi = blockIdx.x;
    const int b  = bi >> 9;
    const int i  = bi & 511;
    const int tid = threadIdx.x, warp = tid >> 5, lane = tid & 31;

    if (tid < 256) {
        int h = tid >> 4, gg = tid & 15;
        wh[gg][h] = __float2half_rn(W[tid]);   // A[m=g][k=h] = W[h][g]
    }
    if (tid < 16) { sg[tid] = gamma[tid]; sb[tid] = beta[tid]; }

    // ---- softmax: warp w handles head w, row in registers ----
    {
        const int h = warp;
        const float* row = &dots[((size_t)(b * HEADS + h) * SEQ + i) * SEQ];
        float f[16];
        #pragma unroll
        for (int t = 0; t < 4; t++) {
            float4 v = *reinterpret_cast<const float4*>(&row[lane * 16 + t * 4]);
            f[t * 4 + 0] = v.x; f[t * 4 + 1] = v.y;
            f[t * 4 + 2] = v.z; f[t * 4 + 3] = v.w;
        }
        float mx = -1e30f;
        #pragma unroll
        for (int t = 0; t < 16; t++) mx = fmaxf(mx, f[t]);
        #pragma unroll
        for (int o = 16; o > 0; o >>= 1)
            mx = fmaxf(mx, __shfl_xor_sync(0xffffffffu, mx, o));
        float s = 0.f;
        #pragma unroll
        for (int t = 0; t < 16; t++) { f[t] = __expf(f[t] - mx); s += f[t]; }
        #pragma unroll
        for (int o = 16; o > 0; o >>= 1)
            s += __shfl_xor_sync(0xffffffffu, s, o);
        float inv = 1.f / s;
        // store normalized attn fp16 (two uint4 = 16 halves)
        #pragma unroll
        for (int q = 0; q < 2; q++) {
            uint4 u;
            __half2 h0 = __floats2half2_rn(f[q*8+0]*inv, f[q*8+1]*inv);
            __half2 h1 = __floats2half2_rn(f[q*8+2]*inv, f[q*8+3]*inv);
            __half2 h2 = __floats2half2_rn(f[q*8+4]*inv, f[q*8+5]*inv);
            __half2 h3 = __floats2half2_rn(f[q*8+6]*inv, f[q*8+7]*inv);
            u.x = *reinterpret_cast<uint32_t*>(&h0);
            u.y = *reinterpret_cast<uint32_t*>(&h1);
            u.z = *reinterpret_cast<uint32_t*>(&h2);
            u.w = *reinterpret_cast<uint32_t*>(&h3);
            *reinterpret_cast<uint4*>(&sch[h][lane * 16 + q * 8]) = u;
        }
    }
    __syncthreads();

    // ---- mix via tensor cores: warp w handles j in [w*32, w*32+32) ----
    {
        const int jb = warp * 32;
        uint32_t a[4];
        ldsm_x4(a, &wh[lane & 15][(lane >> 4) * 8]);       // A = W^T 16x16
        const int g0 = lane >> 2, c = 2 * (lane & 3);
        #pragma unroll
        for (int p = 0; p < 2; p++) {
            uint32_t bf[4];
            // trans load: rows=h, cols=j  ->  B frags for tiles jb+16p, +8
            ldsm_x4_trans(bf, &sch[lane & 15][jb + p * 16 + (lane >> 4) * 8]);
            float d0[4] = {0.f, 0.f, 0.f, 0.f};
            float d1[4] = {0.f, 0.f, 0.f, 0.f};
            uint32_t b0[2] = { bf[0], bf[1] };
            uint32_t b1[2] = { bf[2], bf[3] };
            mma16(d0, a, b0);
            mma16(d1, a, b1);
            const int j0 = jb + p * 16;
            smix[g0][j0 + c]         = d0[0];
            smix[g0][j0 + c + 1]     = d0[1];
            smix[g0 + 8][j0 + c]     = d0[2];
            smix[g0 + 8][j0 + c + 1] = d0[3];
            smix[g0][j0 + 8 + c]         = d1[0];
            smix[g0][j0 + 8 + c + 1]     = d1[1];
            smix[g0 + 8][j0 + 8 + c]     = d1[2];
            smix[g0 + 8][j0 + 8 + c + 1] = d1[3];
        }
    }
    __syncthreads();

    // ---- LayerNorm over heads, per thread j ----
    {
        const int j = tid;
        float mixed[HEADS];
        #pragma unroll
        for (int gg = 0; gg < HEADS; gg++) mixed[gg] = smix[gg][j];
        float mean = 0.f;
        #pragma unroll
        for (int gg = 0; gg < HEADS; gg++) mean += mixed[gg];
        mean *= (1.f / HEADS);
        float var = 0.f;
        #pragma unroll
        for (int gg = 0; gg < HEADS; gg++) {
            float d = mixed[gg] - mean;
            var = fmaf(d, d, var);
        }
        var *= (1.f / HEADS);
        float inv = rsqrtf(var + 1e-3f);
        #pragma unroll
        for (int gg = 0; gg < HEADS; gg++) {
            float y = (mixed[gg] - mean) * inv * sg[gg] + sb[gg];
            attnh[((size_t)(b * HEADS + gg) * SEQ + i) * SEQ + j] =
                __float2half_rn(y);
        }
    }
}

// ---------------------------------------------------------------------------
extern "C" void kernel_launch(void* const* d_in, const int* in_sizes, int n_in,
                              void* d_out, int out_size)
{
    const float* x        = (const float*)d_in[0];
    const float* w_qkv    = (const float*)d_in[1];
    const float* reattn_w = (const float*)d_in[2];
    const float* ln_gamma = (const float*)d_in[3];
    const float* ln_beta  = (const float*)d_in[4];
    const float* w_out    = (const float*)d_in[5];
    const float* b_out    = (const float*)d_in[6];
    float* out = (float*)d_out;

    __half *xh = nullptr, *qkvh = nullptr, *attnh = nullptr, *avh = nullptr;
    __half *wqkvT = nullptr, *woutT = nullptr, *vT = nullptr;
    float *dots = nullptr;
    cudaGetSymbolAddress((void**)&xh,    g_xh);
    cudaGetSymbolAddress((void**)&qkvh,  g_qkvh);
    cudaGetSymbolAddress((void**)&dots,  g_dots);
    cudaGetSymbolAddress((void**)&attnh, g_attnh);
    cudaGetSymbolAddress((void**)&avh,   g_avh);
    cudaGetSymbolAddress((void**)&wqkvT, g_wqkvT);
    cudaGetSymbolAddress((void**)&woutT, g_woutT);
    cudaGetSymbolAddress((void**)&vT,    g_vT);

    dim3 blk(256);

    // 0) prep
    x_cvt<<<(NTOK * DMODEL) / (256 * 8), blk>>>(x, xh);
    transpose_cvt<<<dim3(QKV_N / 32, DMODEL / 32), blk>>>(w_qkv, wqkvT, DMODEL, QKV_N);
    transpose_cvt<<<dim3(DMODEL / 32, DMODEL / 32), blk>>>(w_out, woutT, DMODEL, DMODEL);

    // 1) QKV projection -> fp16
    hgemm<0, 128, 64, 1024><<<dim3(QKV_N / 64, NTOK / 128), blk>>>(
        xh, wqkvT, nullptr, qkvh);

    // 1b) V transpose
    v_transpose<<<dim3(SEQ / 32, DH / 32, BATCH * HEADS), blk>>>(qkvh, vT);

    // 2) dots -> fp32 (alpha=0.125 in epilogue)
    hgemm<3, 128, 64, 64><<<dim3(SEQ / 64, SEQ / 128, BATCH * HEADS), blk>>>(
        qkvh, qkvh, nullptr, dots);

    // 3) fused softmax + tensor-core head mix + LayerNorm -> fp16
    softmax_mix_ln_kernel<<<BATCH * SEQ, 512>>>(dots, attnh, reattn_w, ln_gamma, ln_beta);

    // 4) AV -> fp16
    hgemm<2, 128, 64, 512><<<dim3(1, SEQ / 128, BATCH * HEADS), blk>>>(
        attnh, vT, nullptr, avh);

    // 5) output projection + bias -> fp32
    hgemm<1, 128, 64, 1024><<<dim3(DMODEL / 64, NTOK / 128), blk>>>(
        avh, woutT, b_out, out);
}

// round 16
// speedup vs baseline: 1.0910x; 1.0244x over previous
#include <cuda_runtime.h>
#include <cuda_fp16.h>
#include <stdint.h>
#include <math.h>

#define HEADS 16
#define DH    64
#define BATCH 8
#define SEQ   512
#define DMODEL 1024
#define INNER 1024            // HEADS*DH
#define QKV_N 3072            // 3*INNER
#define NTOK  4096            // BATCH*SEQ

// Scratch (device globals: allocation-free, graph-capture safe)
__device__ __half g_xh[(size_t)NTOK * DMODEL];               // 8 MB
__device__ __half g_qkvh[(size_t)NTOK * QKV_N];              // 24 MB
__device__ float  g_dots[(size_t)BATCH * HEADS * SEQ * SEQ]; // 128 MB fp32 logits
__device__ __half g_attnh[(size_t)BATCH * HEADS * SEQ * SEQ];// 64 MB
__device__ __half g_avh[(size_t)NTOK * INNER];               // 8 MB
__device__ __half g_wqkvT[(size_t)QKV_N * DMODEL];           // 6 MB [n][k]
__device__ __half g_woutT[(size_t)DMODEL * INNER];           // 2 MB [n][k]

// ---------------------------------------------------------------------------
__device__ __forceinline__ void mma16(float* c, const uint32_t* a, const uint32_t* b) {
    asm volatile(
        "mma.sync.aligned.m16n8k16.row.col.f32.f16.f16.f32 "
        "{%0,%1,%2,%3}, {%4,%5,%6,%7}, {%8,%9}, {%0,%1,%2,%3};"
        : "+f"(c[0]), "+f"(c[1]), "+f"(c[2]), "+f"(c[3])
        : "r"(a[0]), "r"(a[1]), "r"(a[2]), "r"(a[3]),
          "r"(b[0]), "r"(b[1]));
}

__device__ __forceinline__ void ldsm_x4(uint32_t* r, const __half* p) {
    uint32_t addr = (uint32_t)__cvta_generic_to_shared(p);
    asm volatile(
        "ldmatrix.sync.aligned.m8n8.x4.shared.b16 {%0,%1,%2,%3}, [%4];"
        : "=r"(r[0]), "=r"(r[1]), "=r"(r[2]), "=r"(r[3]) : "r"(addr));
}

__device__ __forceinline__ void ldsm_x4_trans(uint32_t* r, const __half* p) {
    uint32_t addr = (uint32_t)__cvta_generic_to_shared(p);
    asm volatile(
        "ldmatrix.sync.aligned.m8n8.x4.trans.shared.b16 {%0,%1,%2,%3}, [%4];"
        : "=r"(r[0]), "=r"(r[1]), "=r"(r[2]), "=r"(r[3]) : "r"(addr));
}

__device__ __forceinline__ void cp16(uint32_t smem_dst, const void* gsrc) {
    asm volatile("cp.async.cg.shared.global [%0], [%1], 16;"
                 :: "r"(smem_dst), "l"(gsrc));
}

// ---------------------------------------------------------------------------
// Prep kernels
// ---------------------------------------------------------------------------
__global__ void __launch_bounds__(256) x_cvt(
    const float* __restrict__ in, __half* __restrict__ out)
{
    size_t i = ((size_t)blockIdx.x * 256 + threadIdx.x) * 8;
    float4 a = *reinterpret_cast<const float4*>(in + i);
    float4 b = *reinterpret_cast<const float4*>(in + i + 4);
    __half2 h0 = __floats2half2_rn(a.x, a.y);
    __half2 h1 = __floats2half2_rn(a.z, a.w);
    __half2 h2 = __floats2half2_rn(b.x, b.y);
    __half2 h3 = __floats2half2_rn(b.z, b.w);
    uint4 u;
    u.x = *reinterpret_cast<uint32_t*>(&h0);
    u.y = *reinterpret_cast<uint32_t*>(&h1);
    u.z = *reinterpret_cast<uint32_t*>(&h2);
    u.w = *reinterpret_cast<uint32_t*>(&h3);
    *reinterpret_cast<uint4*>(out + i) = u;
}

// One launch transposes+converts BOTH weight matrices:
// bx < 96: w_qkv [1024 x 3072] -> wqkvT ;  bx >= 96: w_out [1024 x 1024] -> woutT
__global__ void __launch_bounds__(256) weights_prep(
    const float* __restrict__ wqkv, __half* __restrict__ wqkvT,
    const float* __restrict__ wout, __half* __restrict__ woutT)
{
    __shared__ float tile[32][33];
    const bool second = (blockIdx.x >= 96);
    const float* in  = second ? wout  : wqkv;
    __half* out      = second ? woutT : wqkvT;
    const int N      = second ? DMODEL : QKV_N;
    const int n0 = (second ? (blockIdx.x - 96) : blockIdx.x) * 32;
    const int k0 = blockIdx.y * 32;
    const int tx = threadIdx.x & 31, ty = threadIdx.x >> 5;
    #pragma unroll
    for (int t = 0; t < 4; t++)
        tile[ty + t * 8][tx] = in[(size_t)(k0 + ty + t * 8) * N + n0 + tx];
    __syncthreads();
    #pragma unroll
    for (int t = 0; t < 4; t++)
        out[(size_t)(n0 + ty + t * 8) * DMODEL + k0 + tx] =
            __float2half_rn(tile[tx][ty + t * 8]);
}

// ---------------------------------------------------------------------------
// fp16 tensor-core GEMM: cp.async 2-stage, BK=64/stage, ldmatrix fragments.
// MODE 0: QKV (C fp16, B n-major)   MODE 1: OUT (+bias, C fp32, B n-major)
// MODE 2: AV  (per bh, C fp16, B = V k-major in qkvh, trans-ldsm)
// MODE 3: DOTS(per bh, C fp32, *0.125, B n-major rows = K tokens)
// ---------------------------------------------------------------------------
template<int MODE, int BM, int BN, int KTOT>
__global__ void __launch_bounds__(256, 3) hgemm(
    const __half* __restrict__ gA, const __half* __restrict__ gB,
    const float* __restrict__ bias, void* __restrict__ gC)
{
    constexpr bool CHALF  = (MODE == 0 || MODE == 2);
    constexpr bool BTRANS = (MODE == 2);          // B stored [k][n] row-major
    constexpr int MI = BM / 64;
    constexpr int NP = BN / 32;
    constexpr int LK = 72;
    constexpr int S  = 2;
    constexpr int BK = 64;
    constexpr int T  = KTOT / BK;
    constexpr int NLDA = BM / 32;
    // B tile rows: n-major -> BN rows of BK halves; trans -> BK rows of BN halves
    constexpr int BROWS = BTRANS ? BK : BN;
    constexpr int BRC   = BTRANS ? (BN / 16) : (BK / 16);  // 16B chunks per row... (both 64 ->8)
    constexpr int NLDB  = BROWS / 32;

    __shared__ __align__(16) __half sA[S][BM * LK];
    __shared__ __align__(16) __half sB[S][BROWS * LK];

    const int tid  = threadIdx.x;
    const int row0 = blockIdx.y * BM;
    const int col0 = blockIdx.x * BN;

    const __half* A;
    const __half* B;
    float*  Cf = nullptr;
    __half* Ch = nullptr;
    int lda, ldb, ldc;
    float alpha = 1.0f;

    if (MODE == 0) {
        A = gA; lda = DMODEL; B = gB; ldb = DMODEL;
        Ch = (__half*)gC; ldc = QKV_N;
    } else if (MODE == 1) {
        A = gA; lda = DMODEL; B = gB; ldb = DMODEL;
        Cf = (float*)gC; ldc = DMODEL;
    } else if (MODE == 2) {
        const int bh = blockIdx.z, b = bh >> 4, h = bh & 15;
        A = gA + (size_t)bh * SEQ * SEQ;            lda = SEQ;
        // B = V rows j (k-major): qkvh[b][j][2*INNER + h*64 + d]
        B = gB + (size_t)b * SEQ * QKV_N + 2 * INNER + (size_t)h * DH;
        ldb = QKV_N;
        Ch = (__half*)gC + (size_t)b * SEQ * INNER + (size_t)h * DH; ldc = INNER;
    } else {
        const int bh = blockIdx.z, b = bh >> 4, h = bh & 15;
        A = gA + (size_t)b * SEQ * QKV_N + (size_t)h * DH;          lda = QKV_N;
        B = gB + (size_t)b * SEQ * QKV_N + INNER + (size_t)h * DH;  ldb = QKV_N;
        Cf = (float*)gC + (size_t)bh * SEQ * SEQ;                   ldc = SEQ;
        alpha = 0.125f;
    }

    const int warp = tid >> 5, lane = tid & 31;
    const int wm = warp >> 1, wn = warp & 1;
    const int g = lane >> 2, t4 = lane & 3;
    const int lmRow = lane & 15;
    const int lmK8  = (lane >> 4) * 8;

    const int cR = tid >> 3;
    const int cC = tid & 7;

    const uint32_t sA0 = (uint32_t)__cvta_generic_to_shared(&sA[0][0]);
    const uint32_t sB0 = (uint32_t)__cvta_generic_to_shared(&sB[0][0]);

    auto cpStage = [&](int kt, int st) {
        const int k0 = kt * BK;
        #pragma unroll
        for (int p = 0; p < NLDA; p++) {
            int r = cR + p * 32;
            cp16(sA0 + (uint32_t)((st * BM + r) * LK + cC * 8) * 2,
                 &A[(size_t)(row0 + r) * lda + k0 + cC * 8]);
        }
        #pragma unroll
        for (int p = 0; p < NLDB; p++) {
            int r = cR + p * 32;
            if (BTRANS) {
                // rows = k tokens (k0 + r), cols = n within [col0, col0+BN)
                cp16(sB0 + (uint32_t)((st * BROWS + r) * LK + cC * 8) * 2,
                     &B[(size_t)(k0 + r) * ldb + col0 + cC * 8]);
            } else {
                cp16(sB0 + (uint32_t)((st * BROWS + r) * LK + cC * 8) * 2,
                     &B[(size_t)(col0 + r) * ldb + k0 + cC * 8]);
            }
        }
    };

    float acc[MI][NP * 2][4] = {};

    cpStage(0, 0);
    asm volatile("cp.async.commit_group;");

    for (int t = 0; t < T; t++) {
        asm volatile("cp.async.wait_group 0;");
        __syncthreads();

        if (t + 1 < T) cpStage(t + 1, (t + 1) & 1);
        asm volatile("cp.async.commit_group;");

        const __half* cA = sA[t & 1];
        const __half* cB = sB[t & 1];

        #pragma unroll
        for (int kk = 0; kk < 4; kk++) {
            const int kc = kk * 16 + lmK8;
            uint32_t af[MI][4];
            #pragma unroll
            for (int mi = 0; mi < MI; mi++) {
                int r = wm * (BM / 4) + mi * 16 + lmRow;
                ldsm_x4(af[mi], &cA[r * LK + kc]);
            }
            uint32_t bfp[NP][4];
            #pragma unroll
            for (int p = 0; p < NP; p++) {
                if (BTRANS) {
                    // rows = k (kk*16 + lane&15), col-half select by lane>>4
                    ldsm_x4_trans(bfp[p],
                        &cB[(kk * 16 + lmRow) * LK +
                            wn * (BN / 2) + p * 16 + lmK8]);
                } else {
                    int c = wn * (BN / 2) + p * 16 + lmRow;
                    ldsm_x4(bfp[p], &cB[c * LK + kc]);
                }
            }
            #pragma unroll
            for (int mi = 0; mi < MI; mi++)
                #pragma unroll
                for (int p = 0; p < NP; p++) {
                    uint32_t b0[2], b1[2];
                    if (BTRANS) {
                        b0[0] = bfp[p][0]; b0[1] = bfp[p][1];
                        b1[0] = bfp[p][2]; b1[1] = bfp[p][3];
                    } else {
                        b0[0] = bfp[p][0]; b0[1] = bfp[p][2];
                        b1[0] = bfp[p][1]; b1[1] = bfp[p][3];
                    }
                    mma16(acc[mi][2 * p],     af[mi], b0);
                    mma16(acc[mi][2 * p + 1], af[mi], b1);
                }
        }
    }

    #pragma unroll
    for (int mi = 0; mi < MI; mi++) {
        int r = row0 + wm * (BM / 4) + mi * 16 + g;
        #pragma unroll
        for (int ni = 0; ni < NP * 2; ni++) {
            int c = col0 + wn * (BN / 2) + (ni >> 1) * 16 + (ni & 1) * 8 + 2 * t4;
            float* a = acc[mi][ni];
            if (CHALF) {
                __half2 hv0 = __floats2half2_rn(a[0], a[1]);
                __half2 hv1 = __floats2half2_rn(a[2], a[3]);
                *reinterpret_cast<__half2*>(&Ch[(size_t)r * ldc + c]) = hv0;
                *reinterpret_cast<__half2*>(&Ch[(size_t)(r + 8) * ldc + c]) = hv1;
            } else {
                float b0 = 0.f, b1 = 0.f;
                if (MODE == 1) { b0 = bias[c]; b1 = bias[c + 1]; }
                float2 v0, v1;
                v0.x = a[0] * alpha + b0; v0.y = a[1] * alpha + b1;
                v1.x = a[2] * alpha + b0; v1.y = a[3] * alpha + b1;
                *reinterpret_cast<float2*>(&Cf[(size_t)r * ldc + c]) = v0;
                *reinterpret_cast<float2*>(&Cf[(size_t)(r + 8) * ldc + c]) = v1;
            }
        }
    }
}

// ---------------------------------------------------------------------------
// Fused softmax + tensor-core head-mix + LayerNorm (R14-proven).
// ---------------------------------------------------------------------------
__global__ void __launch_bounds__(512) softmax_mix_ln_kernel(
    const float* __restrict__ dots, __half* __restrict__ attnh,
    const float* __restrict__ W,
    const float* __restrict__ gamma, const float* __restrict__ beta)
{
    __shared__ __align__(16) __half sch[HEADS][520];
    __shared__ float smix[HEADS][516];
    __shared__ __align__(16) __half wh[16][24];
    __shared__ float sg[16], sb[16];

    const int bi = blockIdx.x;
    const int b  = bi >> 9;
    const int i  = bi & 511;
    const int tid = threadIdx.x, warp = tid >> 5, lane = tid & 31;

    if (tid < 256) {
        int h = tid >> 4, gg = tid & 15;
        wh[gg][h] = __float2half_rn(W[tid]);
    }
    if (tid < 16) { sg[tid] = gamma[tid]; sb[tid] = beta[tid]; }

    {
        const int h = warp;
        const float* row = &dots[((size_t)(b * HEADS + h) * SEQ + i) * SEQ];
        float f[16];
        #pragma unroll
        for (int t = 0; t < 4; t++) {
            float4 v = *reinterpret_cast<const float4*>(&row[lane * 16 + t * 4]);
            f[t * 4 + 0] = v.x; f[t * 4 + 1] = v.y;
            f[t * 4 + 2] = v.z; f[t * 4 + 3] = v.w;
        }
        float mx = -1e30f;
        #pragma unroll
        for (int t = 0; t < 16; t++) mx = fmaxf(mx, f[t]);
        #pragma unroll
        for (int o = 16; o > 0; o >>= 1)
            mx = fmaxf(mx, __shfl_xor_sync(0xffffffffu, mx, o));
        float s = 0.f;
        #pragma unroll
        for (int t = 0; t < 16; t++) { f[t] = __expf(f[t] - mx); s += f[t]; }
        #pragma unroll
        for (int o = 16; o > 0; o >>= 1)
            s += __shfl_xor_sync(0xffffffffu, s, o);
        float inv = 1.f / s;
        #pragma unroll
        for (int q = 0; q < 2; q++) {
            uint4 u;
            __half2 h0 = __floats2half2_rn(f[q*8+0]*inv, f[q*8+1]*inv);
            __half2 h1 = __floats2half2_rn(f[q*8+2]*inv, f[q*8+3]*inv);
            __half2 h2 = __floats2half2_rn(f[q*8+4]*inv, f[q*8+5]*inv);
            __half2 h3 = __floats2half2_rn(f[q*8+6]*inv, f[q*8+7]*inv);
            u.x = *reinterpret_cast<uint32_t*>(&h0);
            u.y = *reinterpret_cast<uint32_t*>(&h1);
            u.z = *reinterpret_cast<uint32_t*>(&h2);
            u.w = *reinterpret_cast<uint32_t*>(&h3);
            *reinterpret_cast<uint4*>(&sch[h][lane * 16 + q * 8]) = u;
        }
    }
    __syncthreads();

    {
        const int jb = warp * 32;
        uint32_t a[4];
        ldsm_x4(a, &wh[lane & 15][(lane >> 4) * 8]);
        const int g0 = lane >> 2, c = 2 * (lane & 3);
        #pragma unroll
        for (int p = 0; p < 2; p++) {
            uint32_t bf[4];
            ldsm_x4_trans(bf, &sch[lane & 15][jb + p * 16 + (lane >> 4) * 8]);
            float d0[4] = {0.f, 0.f, 0.f, 0.f};
            float d1[4] = {0.f, 0.f, 0.f, 0.f};
            uint32_t b0[2] = { bf[0], bf[1] };
            uint32_t b1[2] = { bf[2], bf[3] };
            mma16(d0, a, b0);
            mma16(d1, a, b1);
            const int j0 = jb + p * 16;
            smix[g0][j0 + c]         = d0[0];
            smix[g0][j0 + c + 1]     = d0[1];
            smix[g0 + 8][j0 + c]     = d0[2];
            smix[g0 + 8][j0 + c + 1] = d0[3];
            smix[g0][j0 + 8 + c]         = d1[0];
            smix[g0][j0 + 8 + c + 1]     = d1[1];
            smix[g0 + 8][j0 + 8 + c]     = d1[2];
            smix[g0 + 8][j0 + 8 + c + 1] = d1[3];
        }
    }
    __syncthreads();

    {
        const int j = tid;
        float mixed[HEADS];
        #pragma unroll
        for (int gg = 0; gg < HEADS; gg++) mixed[gg] = smix[gg][j];
        float mean = 0.f;
        #pragma unroll
        for (int gg = 0; gg < HEADS; gg++) mean += mixed[gg];
        mean *= (1.f / HEADS);
        float var = 0.f;
        #pragma unroll
        for (int gg = 0; gg < HEADS; gg++) {
            float d = mixed[gg] - mean;
            var = fmaf(d, d, var);
        }
        var *= (1.f / HEADS);
        float inv = rsqrtf(var + 1e-3f);
        #pragma unroll
        for (int gg = 0; gg < HEADS; gg++) {
            float y = (mixed[gg] - mean) * inv * sg[gg] + sb[gg];
            attnh[((size_t)(b * HEADS + gg) * SEQ + i) * SEQ + j] =
                __float2half_rn(y);
        }
    }
}

// ---------------------------------------------------------------------------
extern "C" void kernel_launch(void* const* d_in, const int* in_sizes, int n_in,
                              void* d_out, int out_size)
{
    const float* x        = (const float*)d_in[0];
    const float* w_qkv    = (const float*)d_in[1];
    const float* reattn_w = (const float*)d_in[2];
    const float* ln_gamma = (const float*)d_in[3];
    const float* ln_beta  = (const float*)d_in[4];
    const float* w_out    = (const float*)d_in[5];
    const float* b_out    = (const float*)d_in[6];
    float* out = (float*)d_out;

    __half *xh = nullptr, *qkvh = nullptr, *attnh = nullptr, *avh = nullptr;
    __half *wqkvT = nullptr, *woutT = nullptr;
    float *dots = nullptr;
    cudaGetSymbolAddress((void**)&xh,    g_xh);
    cudaGetSymbolAddress((void**)&qkvh,  g_qkvh);
    cudaGetSymbolAddress((void**)&dots,  g_dots);
    cudaGetSymbolAddress((void**)&attnh, g_attnh);
    cudaGetSymbolAddress((void**)&avh,   g_avh);
    cudaGetSymbolAddress((void**)&wqkvT, g_wqkvT);
    cudaGetSymbolAddress((void**)&woutT, g_woutT);

    dim3 blk(256);

    // 0) prep: x->fp16; both weight transposes in ONE launch
    x_cvt<<<(NTOK * DMODEL) / (256 * 8), blk>>>(x, xh);
    weights_prep<<<dim3(96 + 32, 32), blk>>>(w_qkv, wqkvT, w_out, woutT);

    // 1) QKV projection -> fp16
    hgemm<0, 128, 64, 1024><<<dim3(QKV_N / 64, NTOK / 128), blk>>>(
        xh, wqkvT, nullptr, qkvh);

    // 2) dots -> fp32 (alpha=0.125 in epilogue)
    hgemm<3, 128, 64, 64><<<dim3(SEQ / 64, SEQ / 128, BATCH * HEADS), blk>>>(
        qkvh, qkvh, nullptr, dots);

    // 3) fused softmax + tensor-core head mix + LayerNorm -> fp16
    softmax_mix_ln_kernel<<<BATCH * SEQ, 512>>>(dots, attnh, reattn_w, ln_gamma, ln_beta);

    // 4) AV -> fp16 (V read k-major from qkvh via trans-ldsm; no v_transpose)
    hgemm<2, 128, 64, 512><<<dim3(1, SEQ / 128, BATCH * HEADS), blk>>>(
        attnh, qkvh, nullptr, avh);

    // 5) output projection + bias -> fp32
    hgemm<1, 128, 64, 1024><<<dim3(DMODEL / 64, NTOK / 128), blk>>>(
        avh, woutT, b_out, out);
}

// round 17
// speedup vs baseline: 1.1630x; 1.0660x over previous
#include <cuda_runtime.h>
#include <cuda_fp16.h>
#include <stdint.h>
#include <math.h>

#define HEADS 16
#define DH    64
#define BATCH 8
#define SEQ   512
#define DMODEL 1024
#define INNER 1024            // HEADS*DH
#define QKV_N 3072            // 3*INNER
#define NTOK  4096            // BATCH*SEQ

// Scratch (device globals: allocation-free, graph-capture safe)
__device__ __half g_xh[(size_t)NTOK * DMODEL];               // 8 MB
__device__ __half g_qkvh[(size_t)NTOK * QKV_N];              // 24 MB
__device__ __half g_dotsh[(size_t)BATCH * HEADS * SEQ * SEQ];// 64 MB fp16 logits
__device__ __half g_attnh[(size_t)BATCH * HEADS * SEQ * SEQ];// 64 MB
__device__ __half g_avh[(size_t)NTOK * INNER];               // 8 MB
__device__ __half g_wqkvT[(size_t)QKV_N * DMODEL];           // 6 MB [n][k]
__device__ __half g_woutT[(size_t)DMODEL * INNER];           // 2 MB [n][k]

// ---------------------------------------------------------------------------
__device__ __forceinline__ void mma16(float* c, const uint32_t* a, const uint32_t* b) {
    asm volatile(
        "mma.sync.aligned.m16n8k16.row.col.f32.f16.f16.f32 "
        "{%0,%1,%2,%3}, {%4,%5,%6,%7}, {%8,%9}, {%0,%1,%2,%3};"
        : "+f"(c[0]), "+f"(c[1]), "+f"(c[2]), "+f"(c[3])
        : "r"(a[0]), "r"(a[1]), "r"(a[2]), "r"(a[3]),
          "r"(b[0]), "r"(b[1]));
}

__device__ __forceinline__ void ldsm_x4(uint32_t* r, const __half* p) {
    uint32_t addr = (uint32_t)__cvta_generic_to_shared(p);
    asm volatile(
        "ldmatrix.sync.aligned.m8n8.x4.shared.b16 {%0,%1,%2,%3}, [%4];"
        : "=r"(r[0]), "=r"(r[1]), "=r"(r[2]), "=r"(r[3]) : "r"(addr));
}

__device__ __forceinline__ void ldsm_x4_trans(uint32_t* r, const __half* p) {
    uint32_t addr = (uint32_t)__cvta_generic_to_shared(p);
    asm volatile(
        "ldmatrix.sync.aligned.m8n8.x4.trans.shared.b16 {%0,%1,%2,%3}, [%4];"
        : "=r"(r[0]), "=r"(r[1]), "=r"(r[2]), "=r"(r[3]) : "r"(addr));
}

__device__ __forceinline__ void cp16(uint32_t smem_dst, const void* gsrc) {
    asm volatile("cp.async.cg.shared.global [%0], [%1], 16;"
                 :: "r"(smem_dst), "l"(gsrc));
}

// ---------------------------------------------------------------------------
// Prep: ONE kernel. bx<96: w_qkv transpose; bx in [96,128): w_out transpose;
// bx >= 128: x fp32->fp16 linear convert (64 x-blocks x 32 via blockIdx.y).
// ---------------------------------------------------------------------------
__global__ void __launch_bounds__(256) prep_all(
    const float* __restrict__ x, __half* __restrict__ xh,
    const float* __restrict__ wqkv, __half* __restrict__ wqkvT,
    const float* __restrict__ wout, __half* __restrict__ woutT)
{
    const int bx = blockIdx.x;
    if (bx >= 128) {
        size_t i = (((size_t)(bx - 128) * 32 + blockIdx.y) * 256 + threadIdx.x) * 8;
        float4 a = *reinterpret_cast<const float4*>(x + i);
        float4 b = *reinterpret_cast<const float4*>(x + i + 4);
        __half2 h0 = __floats2half2_rn(a.x, a.y);
        __half2 h1 = __floats2half2_rn(a.z, a.w);
        __half2 h2 = __floats2half2_rn(b.x, b.y);
        __half2 h3 = __floats2half2_rn(b.z, b.w);
        uint4 u;
        u.x = *reinterpret_cast<uint32_t*>(&h0);
        u.y = *reinterpret_cast<uint32_t*>(&h1);
        u.z = *reinterpret_cast<uint32_t*>(&h2);
        u.w = *reinterpret_cast<uint32_t*>(&h3);
        *reinterpret_cast<uint4*>(xh + i) = u;
        return;
    }
    __shared__ float tile[32][33];
    const bool second = (bx >= 96);
    const float* in  = second ? wout  : wqkv;
    __half* out      = second ? woutT : wqkvT;
    const int N      = second ? DMODEL : QKV_N;
    const int n0 = (second ? (bx - 96) : bx) * 32;
    const int k0 = blockIdx.y * 32;
    const int tx = threadIdx.x & 31, ty = threadIdx.x >> 5;
    #pragma unroll
    for (int t = 0; t < 4; t++)
        tile[ty + t * 8][tx] = in[(size_t)(k0 + ty + t * 8) * N + n0 + tx];
    __syncthreads();
    #pragma unroll
    for (int t = 0; t < 4; t++)
        out[(size_t)(n0 + ty + t * 8) * DMODEL + k0 + tx] =
            __float2half_rn(tile[tx][ty + t * 8]);
}

// ---------------------------------------------------------------------------
// fp16 tensor-core GEMM: cp.async 2-stage, BK=64/stage, ldmatrix fragments.
// MODE 0: QKV (C fp16, B n-major)   MODE 1: OUT (+bias, C fp32, B n-major)
// MODE 2: AV  (per bh, C fp16, B = V k-major in qkvh, trans-ldsm)
// MODE 3: DOTS(per bh, C fp16 *0.125, B n-major rows = K tokens)
// ---------------------------------------------------------------------------
template<int MODE, int BM, int BN, int KTOT>
__global__ void __launch_bounds__(256, 3) hgemm(
    const __half* __restrict__ gA, const __half* __restrict__ gB,
    const float* __restrict__ bias, void* __restrict__ gC)
{
    constexpr bool CHALF  = (MODE != 1);
    constexpr bool BTRANS = (MODE == 2);
    constexpr float ALPHA = (MODE == 3) ? 0.125f : 1.0f;
    constexpr int MI = BM / 64;
    constexpr int NP = BN / 32;
    constexpr int LK = 72;
    constexpr int S  = 2;
    constexpr int BK = 64;
    constexpr int T  = KTOT / BK;
    constexpr int NLDA = BM / 32;
    constexpr int BROWS = BTRANS ? BK : BN;
    constexpr int NLDB  = BROWS / 32;

    __shared__ __align__(16) __half sA[S][BM * LK];
    __shared__ __align__(16) __half sB[S][BROWS * LK];

    const int tid  = threadIdx.x;
    const int row0 = blockIdx.y * BM;
    const int col0 = blockIdx.x * BN;

    const __half* A;
    const __half* B;
    float*  Cf = nullptr;
    __half* Ch = nullptr;
    int lda, ldb, ldc;

    if (MODE == 0) {
        A = gA; lda = DMODEL; B = gB; ldb = DMODEL;
        Ch = (__half*)gC; ldc = QKV_N;
    } else if (MODE == 1) {
        A = gA; lda = DMODEL; B = gB; ldb = DMODEL;
        Cf = (float*)gC; ldc = DMODEL;
    } else if (MODE == 2) {
        const int bh = blockIdx.z, b = bh >> 4, h = bh & 15;
        A = gA + (size_t)bh * SEQ * SEQ;            lda = SEQ;
        B = gB + (size_t)b * SEQ * QKV_N + 2 * INNER + (size_t)h * DH;
        ldb = QKV_N;
        Ch = (__half*)gC + (size_t)b * SEQ * INNER + (size_t)h * DH; ldc = INNER;
    } else {
        const int bh = blockIdx.z, b = bh >> 4, h = bh & 15;
        A = gA + (size_t)b * SEQ * QKV_N + (size_t)h * DH;          lda = QKV_N;
        B = gB + (size_t)b * SEQ * QKV_N + INNER + (size_t)h * DH;  ldb = QKV_N;
        Ch = (__half*)gC + (size_t)bh * SEQ * SEQ;                  ldc = SEQ;
    }

    const int warp = tid >> 5, lane = tid & 31;
    const int wm = warp >> 1, wn = warp & 1;
    const int g = lane >> 2, t4 = lane & 3;
    const int lmRow = lane & 15;
    const int lmK8  = (lane >> 4) * 8;

    const int cR = tid >> 3;
    const int cC = tid & 7;

    const uint32_t sA0 = (uint32_t)__cvta_generic_to_shared(&sA[0][0]);
    const uint32_t sB0 = (uint32_t)__cvta_generic_to_shared(&sB[0][0]);

    auto cpStage = [&](int kt, int st) {
        const int k0 = kt * BK;
        #pragma unroll
        for (int p = 0; p < NLDA; p++) {
            int r = cR + p * 32;
            cp16(sA0 + (uint32_t)((st * BM + r) * LK + cC * 8) * 2,
                 &A[(size_t)(row0 + r) * lda + k0 + cC * 8]);
        }
        #pragma unroll
        for (int p = 0; p < NLDB; p++) {
            int r = cR + p * 32;
            if (BTRANS) {
                cp16(sB0 + (uint32_t)((st * BROWS + r) * LK + cC * 8) * 2,
                     &B[(size_t)(k0 + r) * ldb + col0 + cC * 8]);
            } else {
                cp16(sB0 + (uint32_t)((st * BROWS + r) * LK + cC * 8) * 2,
                     &B[(size_t)(col0 + r) * ldb + k0 + cC * 8]);
            }
        }
    };

    float acc[MI][NP * 2][4] = {};

    cpStage(0, 0);
    asm volatile("cp.async.commit_group;");

    for (int t = 0; t < T; t++) {
        asm volatile("cp.async.wait_group 0;");
        __syncthreads();

        if (t + 1 < T) cpStage(t + 1, (t + 1) & 1);
        asm volatile("cp.async.commit_group;");

        const __half* cA = sA[t & 1];
        const __half* cB = sB[t & 1];

        #pragma unroll
        for (int kk = 0; kk < 4; kk++) {
            const int kc = kk * 16 + lmK8;
            uint32_t af[MI][4];
            #pragma unroll
            for (int mi = 0; mi < MI; mi++) {
                int r = wm * (BM / 4) + mi * 16 + lmRow;
                ldsm_x4(af[mi], &cA[r * LK + kc]);
            }
            uint32_t bfp[NP][4];
            #pragma unroll
            for (int p = 0; p < NP; p++) {
                if (BTRANS) {
                    ldsm_x4_trans(bfp[p],
                        &cB[(kk * 16 + lmRow) * LK +
                            wn * (BN / 2) + p * 16 + lmK8]);
                } else {
                    int c = wn * (BN / 2) + p * 16 + lmRow;
                    ldsm_x4(bfp[p], &cB[c * LK + kc]);
                }
            }
            #pragma unroll
            for (int mi = 0; mi < MI; mi++)
                #pragma unroll
                for (int p = 0; p < NP; p++) {
                    uint32_t b0[2], b1[2];
                    if (BTRANS) {
                        b0[0] = bfp[p][0]; b0[1] = bfp[p][1];
                        b1[0] = bfp[p][2]; b1[1] = bfp[p][3];
                    } else {
                        b0[0] = bfp[p][0]; b0[1] = bfp[p][2];
                        b1[0] = bfp[p][1]; b1[1] = bfp[p][3];
                    }
                    mma16(acc[mi][2 * p],     af[mi], b0);
                    mma16(acc[mi][2 * p + 1], af[mi], b1);
                }
        }
    }

    #pragma unroll
    for (int mi = 0; mi < MI; mi++) {
        int r = row0 + wm * (BM / 4) + mi * 16 + g;
        #pragma unroll
        for (int ni = 0; ni < NP * 2; ni++) {
            int c = col0 + wn * (BN / 2) + (ni >> 1) * 16 + (ni & 1) * 8 + 2 * t4;
            float* a = acc[mi][ni];
            if (CHALF) {
                __half2 hv0 = __floats2half2_rn(a[0] * ALPHA, a[1] * ALPHA);
                __half2 hv1 = __floats2half2_rn(a[2] * ALPHA, a[3] * ALPHA);
                *reinterpret_cast<__half2*>(&Ch[(size_t)r * ldc + c]) = hv0;
                *reinterpret_cast<__half2*>(&Ch[(size_t)(r + 8) * ldc + c]) = hv1;
            } else {
                float b0 = bias[c], b1 = bias[c + 1];
                float2 v0, v1;
                v0.x = a[0] + b0; v0.y = a[1] + b1;
                v1.x = a[2] + b0; v1.y = a[3] + b1;
                *reinterpret_cast<float2*>(&Cf[(size_t)r * ldc + c]) = v0;
                *reinterpret_cast<float2*>(&Cf[(size_t)(r + 8) * ldc + c]) = v1;
            }
        }
    }
}

// ---------------------------------------------------------------------------
// Fused softmax + tensor-core head-mix + LayerNorm. Reads fp16 logits.
// ---------------------------------------------------------------------------
__global__ void __launch_bounds__(512) softmax_mix_ln_kernel(
    const __half* __restrict__ dotsh, __half* __restrict__ attnh,
    const float* __restrict__ W,
    const float* __restrict__ gamma, const float* __restrict__ beta)
{
    __shared__ __align__(16) __half sch[HEADS][520];
    __shared__ float smix[HEADS][516];
    __shared__ __align__(16) __half wh[16][24];
    __shared__ float sg[16], sb[16];

    const int bi = blockIdx.x;
    const int b  = bi >> 9;
    const int i  = bi & 511;
    const int tid = threadIdx.x, warp = tid >> 5, lane = tid & 31;

    if (tid < 256) {
        int h = tid >> 4, gg = tid & 15;
        wh[gg][h] = __float2half_rn(W[tid]);
    }
    if (tid < 16) { sg[tid] = gamma[tid]; sb[tid] = beta[tid]; }

    // ---- softmax: warp w handles head w, row in registers (fp16 load) ----
    {
        const int h = warp;
        const __half* row = &dotsh[((size_t)(b * HEADS + h) * SEQ + i) * SEQ];
        float f[16];
        #pragma unroll
        for (int q = 0; q < 2; q++) {
            uint4 u = *reinterpret_cast<const uint4*>(&row[lane * 16 + q * 8]);
            const __half2* hp = reinterpret_cast<const __half2*>(&u);
            #pragma unroll
            for (int k = 0; k < 4; k++) {
                float2 v = __half22float2(hp[k]);
                f[q * 8 + 2 * k]     = v.x;
                f[q * 8 + 2 * k + 1] = v.y;
            }
        }
        float mx = -1e30f;
        #pragma unroll
        for (int t = 0; t < 16; t++) mx = fmaxf(mx, f[t]);
        #pragma unroll
        for (int o = 16; o > 0; o >>= 1)
            mx = fmaxf(mx, __shfl_xor_sync(0xffffffffu, mx, o));
        float s = 0.f;
        #pragma unroll
        for (int t = 0; t < 16; t++) { f[t] = __expf(f[t] - mx); s += f[t]; }
        #pragma unroll
        for (int o = 16; o > 0; o >>= 1)
            s += __shfl_xor_sync(0xffffffffu, s, o);
        float inv = 1.f / s;
        #pragma unroll
        for (int q = 0; q < 2; q++) {
            uint4 u;
            __half2 h0 = __floats2half2_rn(f[q*8+0]*inv, f[q*8+1]*inv);
            __half2 h1 = __floats2half2_rn(f[q*8+2]*inv, f[q*8+3]*inv);
            __half2 h2 = __floats2half2_rn(f[q*8+4]*inv, f[q*8+5]*inv);
            __half2 h3 = __floats2half2_rn(f[q*8+6]*inv, f[q*8+7]*inv);
            u.x = *reinterpret_cast<uint32_t*>(&h0);
            u.y = *reinterpret_cast<uint32_t*>(&h1);
            u.z = *reinterpret_cast<uint32_t*>(&h2);
            u.w = *reinterpret_cast<uint32_t*>(&h3);
            *reinterpret_cast<uint4*>(&sch[h][lane * 16 + q * 8]) = u;
        }
    }
    __syncthreads();

    // ---- mix via tensor cores ----
    {
        const int jb = warp * 32;
        uint32_t a[4];
        ldsm_x4(a, &wh[lane & 15][(lane >> 4) * 8]);
        const int g0 = lane >> 2, c = 2 * (lane & 3);
        #pragma unroll
        for (int p = 0; p < 2; p++) {
            uint32_t bf[4];
            ldsm_x4_trans(bf, &sch[lane & 15][jb + p * 16 + (lane >> 4) * 8]);
            float d0[4] = {0.f, 0.f, 0.f, 0.f};
            float d1[4] = {0.f, 0.f, 0.f, 0.f};
            uint32_t b0[2] = { bf[0], bf[1] };
            uint32_t b1[2] = { bf[2], bf[3] };
            mma16(d0, a, b0);
            mma16(d1, a, b1);
            const int j0 = jb + p * 16;
            smix[g0][j0 + c]         = d0[0];
            smix[g0][j0 + c + 1]     = d0[1];
            smix[g0 + 8][j0 + c]     = d0[2];
            smix[g0 + 8][j0 + c + 1] = d0[3];
            smix[g0][j0 + 8 + c]         = d1[0];
            smix[g0][j0 + 8 + c + 1]     = d1[1];
            smix[g0 + 8][j0 + 8 + c]     = d1[2];
            smix[g0 + 8][j0 + 8 + c + 1] = d1[3];
        }
    }
    __syncthreads();

    // ---- LayerNorm over heads, per thread j ----
    {
        const int j = tid;
        float mixed[HEADS];
        #pragma unroll
        for (int gg = 0; gg < HEADS; gg++) mixed[gg] = smix[gg][j];
        float mean = 0.f;
        #pragma unroll
        for (int gg = 0; gg < HEADS; gg++) mean += mixed[gg];
        mean *= (1.f / HEADS);
        float var = 0.f;
        #pragma unroll
        for (int gg = 0; gg < HEADS; gg++) {
            float d = mixed[gg] - mean;
            var = fmaf(d, d, var);
        }
        var *= (1.f / HEADS);
        float inv = rsqrtf(var + 1e-3f);
        #pragma unroll
        for (int gg = 0; gg < HEADS; gg++) {
            float y = (mixed[gg] - mean) * inv * sg[gg] + sb[gg];
            attnh[((size_t)(b * HEADS + gg) * SEQ + i) * SEQ + j] =
                __float2half_rn(y);
        }
    }
}

// ---------------------------------------------------------------------------
extern "C" void kernel_launch(void* const* d_in, const int* in_sizes, int n_in,
                              void* d_out, int out_size)
{
    const float* x        = (const float*)d_in[0];
    const float* w_qkv    = (const float*)d_in[1];
    const float* reattn_w = (const float*)d_in[2];
    const float* ln_gamma = (const float*)d_in[3];
    const float* ln_beta  = (const float*)d_in[4];
    const float* w_out    = (const float*)d_in[5];
    const float* b_out    = (const float*)d_in[6];
    float* out = (float*)d_out;

    __half *xh = nullptr, *qkvh = nullptr, *attnh = nullptr, *avh = nullptr;
    __half *wqkvT = nullptr, *woutT = nullptr, *dotsh = nullptr;
    cudaGetSymbolAddress((void**)&xh,    g_xh);
    cudaGetSymbolAddress((void**)&qkvh,  g_qkvh);
    cudaGetSymbolAddress((void**)&dotsh, g_dotsh);
    cudaGetSymbolAddress((void**)&attnh, g_attnh);
    cudaGetSymbolAddress((void**)&avh,   g_avh);
    cudaGetSymbolAddress((void**)&wqkvT, g_wqkvT);
    cudaGetSymbolAddress((void**)&woutT, g_woutT);

    dim3 blk(256);

    // 0) prep: x->fp16 + both weight transposes in ONE launch
    prep_all<<<dim3(192, 32), blk>>>(x, xh, w_qkv, wqkvT, w_out, woutT);

    // 1) QKV projection -> fp16
    hgemm<0, 128, 64, 1024><<<dim3(QKV_N / 64, NTOK / 128), blk>>>(
        xh, wqkvT, nullptr, qkvh);

    // 2) dots -> fp16 (alpha=0.125 pre-store; logits ~N(0,1))
    hgemm<3, 128, 64, 64><<<dim3(SEQ / 64, SEQ / 128, BATCH * HEADS), blk>>>(
        qkvh, qkvh, nullptr, dotsh);

    // 3) fused softmax + tensor-core head mix + LayerNorm -> fp16
    softmax_mix_ln_kernel<<<BATCH * SEQ, 512>>>(dotsh, attnh, reattn_w, ln_gamma, ln_beta);

    // 4) AV -> fp16 (V read k-major from qkvh via trans-ldsm)
    hgemm<2, 128, 64, 512><<<dim3(1, SEQ / 128, BATCH * HEADS), blk>>>(
        attnh, qkvh, nullptr, avh);

    // 5) output projection + bias -> fp32
    hgemm<1, 128, 64, 1024><<<dim3(DMODEL / 64, NTOK / 128), blk>>>(
        avh, woutT, b_out, out);
}